// round 1
// baseline (speedup 1.0000x reference)
#include <cuda_runtime.h>
#include <math.h>

// Problem constants (from reference): N_DIM=1024, BATCH=8192.
// Inputs (metadata order): k (8192), w_init (1025), b_init (1025), w (2).
// Output: float32, 8192 elements.
//
// Closed form: the backward induction is a linear recurrence; after N steps
//   out[b] = sum_j C(N,j) w0^{N-j} w1^j * relu(k[b]*w_init[j] + b_init[j])

#define N_DIM   1024
#define N_NODES (N_DIM + 1)
#define BATCH   8192

// Scratch: binomial-weighted coefficients (no cudaMalloc allowed).
__device__ float g_coeff[N_NODES];

// ---------------------------------------------------------------------------
// Kernel 1: compute c_j = C(N,j) * w0^(N-j) * w1^j via log-space fp64.
// Tiny (1025 threads), runs once per launch (deterministic).
// ---------------------------------------------------------------------------
__global__ void coeff_kernel(const float* __restrict__ w)
{
    int j = blockIdx.x * blockDim.x + threadIdx.x;
    if (j >= N_NODES) return;

    double lw0 = log((double)w[0]);
    double lw1 = log((double)w[1]);

    double lc = lgamma((double)(N_DIM + 1))
              - lgamma((double)(j + 1))
              - lgamma((double)(N_DIM - j + 1))
              + (double)(N_DIM - j) * lw0
              + (double)j * lw1;

    g_coeff[j] = (float)exp(lc);
}

// ---------------------------------------------------------------------------
// Kernel 2: one warp per batch element.
//   out[b] = sum_j c_j * relu(k[b]*w_init[j] + b_init[j])
// Lanes stride j by 32 -> coalesced loads of c/w_init/b_init (12 KB total,
// L1/L2 resident for every warp). Warp shfl reduction, lane 0 writes.
// ---------------------------------------------------------------------------
__global__ __launch_bounds__(256)
void price_kernel(const float* __restrict__ k,
                  const float* __restrict__ w_init,
                  const float* __restrict__ b_init,
                  float* __restrict__ out)
{
    int gtid = blockIdx.x * blockDim.x + threadIdx.x;
    int warp = gtid >> 5;
    int lane = gtid & 31;
    if (warp >= BATCH) return;

    float kv  = __ldg(&k[warp]);
    float acc = 0.0f;

    #pragma unroll 4
    for (int j = lane; j < N_NODES; j += 32) {
        float x = fmaf(kv, __ldg(&w_init[j]), __ldg(&b_init[j]));
        x = fmaxf(x, 0.0f);
        acc = fmaf(g_coeff[j], x, acc);
    }

    #pragma unroll
    for (int off = 16; off > 0; off >>= 1)
        acc += __shfl_down_sync(0xFFFFFFFFu, acc, off);

    if (lane == 0) out[warp] = acc;
}

// ---------------------------------------------------------------------------
extern "C" void kernel_launch(void* const* d_in, const int* in_sizes, int n_in,
                              void* d_out, int out_size)
{
    const float* k      = (const float*)d_in[0];   // (8192,)
    const float* w_init = (const float*)d_in[1];   // (1025,)
    const float* b_init = (const float*)d_in[2];   // (1025,)
    const float* w      = (const float*)d_in[3];   // (2,)
    float*       out    = (float*)d_out;           // (8192,)

    (void)in_sizes; (void)n_in; (void)out_size;

    coeff_kernel<<<(N_NODES + 255) / 256, 256>>>(w);

    // 8192 warps -> 8192*32 threads -> 1024 blocks of 256
    price_kernel<<<(BATCH * 32) / 256, 256>>>(k, w_init, b_init, out);
}